// round 1
// baseline (speedup 1.0000x reference)
#include <cuda_runtime.h>
#include <cstdint>
#include <cstddef>

// ---------------------------------------------------------------------------
// Problem constants
// ---------------------------------------------------------------------------
#define TOK   8192          // B*S tokens
#define DC    512
#define DM    2048

// GEMM tile config
#define BM      64
#define BN      512
#define BK      16
#define STAGES  3
#define AW      (BM*(BK+4))          // 1280 words  (A stage, padded rows)
#define BW      (BN*(BK+4))          // 10240 words (B stage, padded rows)
#define STW     (AW+BW)              // 11520 words per stage
#define CSTR    516                  // smemC row stride (words)
#define SMEM_WORDS (STW*STAGES)      // 34560 words = 138240 bytes
#define SMEM_BYTES (SMEM_WORDS*4)
#define SPREC_OFF  (64*CSTR)         // 33024 words; sigmoid table after smC

// ---------------------------------------------------------------------------
// Device scratch (no cudaMalloc allowed)
// ---------------------------------------------------------------------------
__device__ float g_cat [TOK * DM];       // 67 MB  (concat of 4 projections)
__device__ float g_x0  [TOK * DC];       // 16.8 MB
__device__ float g_acts[4 * TOK * DC];   // 67 MB
__device__ float g_pred[2 * TOK * DC];   // 33.6 MB
__device__ float g_comp[TOK * DC];       // 16.8 MB
__device__ float g_h   [TOK * DC];       // 16.8 MB

// ---------------------------------------------------------------------------
// PTX helpers
// ---------------------------------------------------------------------------
__device__ __forceinline__ void cp16(void* d, const void* s) {
    unsigned a = (unsigned)__cvta_generic_to_shared(d);
    asm volatile("cp.async.cg.shared.global [%0], [%1], 16;\n" :: "r"(a), "l"(s));
}
__device__ __forceinline__ void cpcommit() { asm volatile("cp.async.commit_group;\n"); }
__device__ __forceinline__ void cpwait1()  { asm volatile("cp.async.wait_group 1;\n"); }

__device__ __forceinline__ void mma_tf32(float* d, const uint32_t* a, const uint32_t* b) {
    asm volatile(
        "mma.sync.aligned.m16n8k8.row.col.f32.tf32.tf32.f32 "
        "{%0,%1,%2,%3}, {%4,%5,%6,%7}, {%8,%9}, {%0,%1,%2,%3};\n"
        : "+f"(d[0]), "+f"(d[1]), "+f"(d[2]), "+f"(d[3])
        : "r"(a[0]), "r"(a[1]), "r"(a[2]), "r"(a[3]), "r"(b[0]), "r"(b[1]));
}

enum { EPI_BIAS = 0, EPI_LN = 1, EPI_UPD = 2, EPI_GELU = 3, EPI_ADD = 4 };

// ---------------------------------------------------------------------------
// One GEMM kernel: y[t, n] = epilogue( sum_k A[t,k] * W[n,k] + bias[n] )
//   CTA tile: 64 rows x 512 cols (full feature row -> LN fusable in epilogue)
//   grid.x = TOK/64, grid.y = N_total/512 (column blocks, for the N=2048 head)
// ---------------------------------------------------------------------------
template<int EPI>
__global__ void __launch_bounds__(256, 1) gemm_k(
    const float* A, size_t ldA,
    const float* __restrict__ Wm, int K,
    const float* __restrict__ bias,
    const float* __restrict__ lng, const float* __restrict__ lnbv,
    const float* comp, const float* target,
    const float* actsP, const float* __restrict__ logit,
    const float* __restrict__ qwen,
    float* out, size_t ldOut)
{
    extern __shared__ float sm[];
    const int tid  = threadIdx.x;
    const int wid  = tid >> 5;
    const int lane = tid & 31;
    const int g    = lane >> 2;      // 0..7
    const int t    = lane & 3;       // 0..3
    const size_t bm0 = (size_t)blockIdx.x * BM;
    const int by     = blockIdx.y;
    const float* Wp    = Wm + (size_t)by * 512 * (size_t)K;
    const float* biasP = bias + by * 512;
    const int colOff   = by * 512;
    const int KT = K / BK;

    float acc[4][8][4];
#pragma unroll
    for (int mi = 0; mi < 4; mi++)
#pragma unroll
        for (int ni = 0; ni < 8; ni++)
#pragma unroll
            for (int q = 0; q < 4; q++) acc[mi][ni][q] = 0.f;

    auto load_stage = [&](int s, int kt) {
        float* dA = sm + s * STW;
        float* dB = dA + AW;
        const int k0 = kt * BK;
        {   // A tile: 64 x 16 floats -> 256 x 16B chunks, 1 per thread
            int r = tid >> 2, cc = (tid & 3) * 4;
            cp16(dA + r * (BK + 4) + cc, A + (bm0 + (size_t)r) * ldA + k0 + cc);
        }
#pragma unroll
        for (int j = 0; j < 8; j++) {   // B tile: 512 x 16 floats -> 2048 chunks
            int idx = tid + j * 256;
            int r = idx >> 2, cc = (idx & 3) * 4;
            cp16(dB + r * (BK + 4) + cc, Wp + (size_t)r * (size_t)K + k0 + cc);
        }
    };

    load_stage(0, 0); cpcommit();
    load_stage(1, 1); cpcommit();

    for (int kt = 0; kt < KT; kt++) {
        cpwait1();
        __syncthreads();
        const float* sA = sm + (kt % STAGES) * STW;
        const float* sB = sA + AW;
#pragma unroll
        for (int ks = 0; ks < 2; ks++) {
            uint32_t a[4][4], b[8][2];
#pragma unroll
            for (int mi = 0; mi < 4; mi++) {
                int r = mi * 16 + g, c = ks * 8 + t;
                a[mi][0] = __float_as_uint(sA[r       * (BK + 4) + c]);
                a[mi][1] = __float_as_uint(sA[(r + 8) * (BK + 4) + c]);
                a[mi][2] = __float_as_uint(sA[r       * (BK + 4) + c + 4]);
                a[mi][3] = __float_as_uint(sA[(r + 8) * (BK + 4) + c + 4]);
            }
#pragma unroll
            for (int ni = 0; ni < 8; ni++) {
                int cB = wid * 64 + ni * 8 + g;
                b[ni][0] = __float_as_uint(sB[cB * (BK + 4) + ks * 8 + t]);
                b[ni][1] = __float_as_uint(sB[cB * (BK + 4) + ks * 8 + t + 4]);
            }
#pragma unroll
            for (int mi = 0; mi < 4; mi++)
#pragma unroll
                for (int ni = 0; ni < 8; ni++)
                    mma_tf32(acc[mi][ni], a[mi], b[ni]);
        }
        __syncthreads();
        if (kt + STAGES - 1 < KT) load_stage((kt + STAGES - 1) % STAGES, kt + STAGES - 1);
        cpcommit();
    }

    // ---------------- epilogue: dump accumulators through SMEM ----------------
    __syncthreads();
    float* smC = sm;
#pragma unroll
    for (int mi = 0; mi < 4; mi++)
#pragma unroll
        for (int ni = 0; ni < 8; ni++) {
            int r = mi * 16 + g, c = wid * 64 + ni * 8 + 2 * t;
            smC[r       * CSTR + c]     = acc[mi][ni][0];
            smC[r       * CSTR + c + 1] = acc[mi][ni][1];
            smC[(r + 8) * CSTR + c]     = acc[mi][ni][2];
            smC[(r + 8) * CSTR + c + 1] = acc[mi][ni][3];
        }
    if (EPI == EPI_UPD) {   // precompute sigmoid(precision_logit) once per CTA
        float* sprec = sm + SPREC_OFF;
#pragma unroll
        for (int j = 0; j < 2; j++) {
            int n = tid + j * 256;
            sprec[n] = 1.f / (1.f + expf(-logit[n]));
        }
    }
    __syncthreads();

    const float* sprec = sm + SPREC_OFF;
#pragma unroll 1
    for (int rr = 0; rr < 8; rr++) {          // each warp owns 8 rows
        const int row = wid * 8 + rr;
        const size_t tg = bm0 + row;
        if (EPI == EPI_LN || EPI == EPI_UPD) {
            float v[16];
#pragma unroll
            for (int j = 0; j < 16; j++) {
                int n = lane + 32 * j;
                float av = smC[row * CSTR + n] + biasP[n];
                if (EPI == EPI_LN) {
                    v[j] = av;
                } else {
                    float cv = comp  [tg * DC + n];
                    float tv = target[tg * DC + n];
                    float ao = actsP [tg * DC + n];
                    v[j] = ao + 0.5f * (cv - tv) * sprec[n] + 0.1f * av;
                }
            }
            float s = 0.f;
#pragma unroll
            for (int j = 0; j < 16; j++) s += v[j];
#pragma unroll
            for (int o = 16; o > 0; o >>= 1) s += __shfl_xor_sync(0xffffffffu, s, o);
            const float mean = s * (1.0f / 512.0f);
            float q = 0.f;
#pragma unroll
            for (int j = 0; j < 16; j++) { float d = v[j] - mean; q += d * d; }
#pragma unroll
            for (int o = 16; o > 0; o >>= 1) q += __shfl_xor_sync(0xffffffffu, q, o);
            const float rstd = rsqrtf(q * (1.0f / 512.0f) + 1e-5f);
#pragma unroll
            for (int j = 0; j < 16; j++) {
                int n = lane + 32 * j;
                out[tg * ldOut + n] = (v[j] - mean) * rstd * lng[n] + lnbv[n];
            }
        } else {
#pragma unroll
            for (int j = 0; j < 16; j++) {
                int n = lane + 32 * j;
                float av = smC[row * CSTR + n] + biasP[n];
                float y;
                if (EPI == EPI_BIAS)      y = av;
                else if (EPI == EPI_GELU) y = 0.5f * av * (1.f + erff(av * 0.70710678118f));
                else                      y = av + qwen[tg * (size_t)DM + colOff + n];
                out[tg * ldOut + colOff + n] = y;
            }
        }
    }
}

// ---------------------------------------------------------------------------
// Host orchestration (fully graph-capturable: kernel launches only)
// ---------------------------------------------------------------------------
extern "C" void kernel_launch(void* const* d_in, const int* in_sizes, int n_in,
                              void* d_out, int out_size)
{
    const float* qwen   = (const float*)d_in[0];
    const float* obs    = (const float*)d_in[1];
    const float* proj_W = (const float*)d_in[2];
    const float* proj_b = (const float*)d_in[3];
    const float* fuse_W = (const float*)d_in[4];
    const float* fuse_b = (const float*)d_in[5];
    const float* up_W   = (const float*)d_in[6];
    const float* up_b   = (const float*)d_in[7];
    const float* lat_W  = (const float*)d_in[8];
    const float* lat_b  = (const float*)d_in[9];
    const float* plog   = (const float*)d_in[10];
    const float* ln_g   = (const float*)d_in[11];
    const float* ln_b   = (const float*)d_in[12];
    const float* down_W = (const float*)d_in[13];
    const float* down_b = (const float*)d_in[14];
    const float* out1_W = (const float*)d_in[15];
    const float* out1_b = (const float*)d_in[16];
    const float* out2_W = (const float*)d_in[17];
    const float* out2_b = (const float*)d_in[18];
    float* out = (float*)d_out;

    float *cat, *x0, *acts, *pred, *comp, *hbuf;
    cudaGetSymbolAddress((void**)&cat,  g_cat);
    cudaGetSymbolAddress((void**)&x0,   g_x0);
    cudaGetSymbolAddress((void**)&acts, g_acts);
    cudaGetSymbolAddress((void**)&pred, g_pred);
    cudaGetSymbolAddress((void**)&comp, g_comp);
    cudaGetSymbolAddress((void**)&hbuf, g_h);

    cudaFuncSetAttribute(gemm_k<EPI_BIAS>, cudaFuncAttributeMaxDynamicSharedMemorySize, SMEM_BYTES);
    cudaFuncSetAttribute(gemm_k<EPI_LN>,   cudaFuncAttributeMaxDynamicSharedMemorySize, SMEM_BYTES);
    cudaFuncSetAttribute(gemm_k<EPI_UPD>,  cudaFuncAttributeMaxDynamicSharedMemorySize, SMEM_BYTES);
    cudaFuncSetAttribute(gemm_k<EPI_GELU>, cudaFuncAttributeMaxDynamicSharedMemorySize, SMEM_BYTES);
    cudaFuncSetAttribute(gemm_k<EPI_ADD>,  cudaFuncAttributeMaxDynamicSharedMemorySize, SMEM_BYTES);

    const dim3 blk(256);
    const dim3 g1(TOK / BM, 1);
    const dim3 g4(TOK / BM, 4);
    const size_t WSZ = (size_t)DC * DC;   // 512*512 weight matrix stride
    const size_t ASZ = (size_t)TOK * DC;  // one activation buffer

    // ---- input projections -> cat (column blocks of 512) --------------------
    for (int o = 0; o < 4; o++)
        gemm_k<EPI_BIAS><<<g1, blk, SMEM_BYTES>>>(
            obs + (size_t)o * TOK * DM, DM,
            proj_W + (size_t)o * DC * DM, DM, proj_b + o * DC,
            nullptr, nullptr, nullptr, nullptr, nullptr, nullptr, nullptr,
            cat + o * DC, DM);

    // ---- fuse -> x0 ----------------------------------------------------------
    gemm_k<EPI_BIAS><<<g1, blk, SMEM_BYTES>>>(
        cat, DM, fuse_W, DM, fuse_b,
        nullptr, nullptr, nullptr, nullptr, nullptr, nullptr, nullptr,
        x0, DC);

    // ---- initial bottom-up pass ---------------------------------------------
    const float* x = x0;
    for (int i = 0; i < 4; i++) {
        gemm_k<EPI_LN><<<g1, blk, SMEM_BYTES>>>(
            x, DC, up_W + i * WSZ, DC, up_b + i * DC,
            ln_g + i * DC, ln_b + i * DC,
            nullptr, nullptr, nullptr, nullptr, nullptr,
            acts + i * ASZ, DC);
        x = acts + i * ASZ;
    }

    // ---- settling -----------------------------------------------------------
    for (int s = 0; s < 5; s++) {
        // preds from PRE-sweep activations
        gemm_k<EPI_BIAS><<<g1, blk, SMEM_BYTES>>>(
            acts + 2 * ASZ, DC, down_W + 2 * WSZ, DC, down_b + 2 * DC,
            nullptr, nullptr, nullptr, nullptr, nullptr, nullptr, nullptr,
            pred + 1 * ASZ, DC);
        gemm_k<EPI_BIAS><<<g1, blk, SMEM_BYTES>>>(
            acts + 1 * ASZ, DC, down_W + 1 * WSZ, DC, down_b + 1 * DC,
            nullptr, nullptr, nullptr, nullptr, nullptr, nullptr, nullptr,
            pred + 0 * ASZ, DC);

        x = x0;
        for (int i = 0; i < 4; i++) {
            float* ai = acts + i * ASZ;
            // compressed = LN(x @ up.T + up_b)
            gemm_k<EPI_LN><<<g1, blk, SMEM_BYTES>>>(
                x, DC, up_W + i * WSZ, DC, up_b + i * DC,
                ln_g + i * DC, ln_b + i * DC,
                nullptr, nullptr, nullptr, nullptr, nullptr,
                comp, DC);
            // acts[i] = LN(acts[i] + 0.5*(comp - target)*sigmoid(logit) + 0.1*(acts[i]@lat.T + lat_b))
            const float* targ = (i < 2) ? (pred + (size_t)i * ASZ) : ai;
            gemm_k<EPI_UPD><<<g1, blk, SMEM_BYTES>>>(
                ai, DC, lat_W + i * WSZ, DC, lat_b + i * DC,
                ln_g + i * DC, ln_b + i * DC,
                comp, targ, ai, plog + i * DC, nullptr,
                ai, DC);
            x = ai;
        }
    }

    // ---- output head --------------------------------------------------------
    gemm_k<EPI_GELU><<<g1, blk, SMEM_BYTES>>>(
        acts + 3 * ASZ, DC, out1_W, DC, out1_b,
        nullptr, nullptr, nullptr, nullptr, nullptr, nullptr, nullptr,
        hbuf, DC);
    gemm_k<EPI_ADD><<<g4, blk, SMEM_BYTES>>>(
        hbuf, DC, out2_W, DC, out2_b,
        nullptr, nullptr, nullptr, nullptr, nullptr, nullptr,
        qwen, out, DM);
    (void)in_sizes; (void)n_in; (void)out_size;
}

// round 3
// speedup vs baseline: 2.4012x; 2.4012x over previous
#include <cuda_runtime.h>
#include <cuda_fp16.h>
#include <cstdint>
#include <cstddef>

// ---------------------------------------------------------------------------
// Problem constants
// ---------------------------------------------------------------------------
#define TOK   8192
#define DC    512
#define DM    2048

#define BM    64            // tokens per CTA tile
#define BKH   64            // halfs per K-tile = 128 bytes/row (SW128)

#define STAGE_A   (BM * 128)       // 8192  B
#define STAGE_B   (512 * 128)      // 65536 B
#define STAGE_BYTES (STAGE_A + STAGE_B)      // 73728
#define SMEM_BYTES  (2 * STAGE_BYTES)        // 147456

// SW128 swizzle on byte offsets within a tile (16B granular)
#define SWZ(x) ((x) ^ (((x) >> 3) & 0x70))

// ---------------------------------------------------------------------------
// Device scratch (half precision activations + converted weights)
// ---------------------------------------------------------------------------
__device__ __half g_obsh[(size_t)4 * TOK * DM];   // 134 MB
__device__ __half g_wh[9437184];                  // all converted weights
__device__ __half g_cat [(size_t)TOK * DM];
__device__ __half g_x0  [TOK * DC];
__device__ __half g_acts[4 * TOK * DC];
__device__ __half g_pred[2 * TOK * DC];
__device__ __half g_comp[TOK * DC];
__device__ __half g_h   [TOK * DC];

// weight offsets inside g_wh
#define W_PROJ 0
#define W_FUSE (W_PROJ + 4*DC*DM)          // 4194304
#define W_UP   (W_FUSE + DC*4*DC)          // +1048576
#define W_LAT  (W_UP   + 4*DC*DC)
#define W_DOWN (W_LAT  + 4*DC*DC)
#define W_OUT1 (W_DOWN + 3*DC*DC)
#define W_OUT2 (W_OUT1 + DC*DC)

// ---------------------------------------------------------------------------
// PTX helpers
// ---------------------------------------------------------------------------
__device__ __forceinline__ uint32_t smem_u32(const void* p) {
    uint32_t a;
    asm("{ .reg .u64 t; cvta.to.shared.u64 t, %1; cvt.u32.u64 %0, t; }"
        : "=r"(a) : "l"(p));
    return a;
}
__device__ __forceinline__ void cp16(uint32_t d, const void* s) {
    asm volatile("cp.async.cg.shared.global [%0], [%1], 16;\n" :: "r"(d), "l"(s));
}
__device__ __forceinline__ void ldsm4(uint32_t& r0, uint32_t& r1,
                                      uint32_t& r2, uint32_t& r3, uint32_t a) {
    asm volatile("ldmatrix.sync.aligned.m8n8.x4.shared.b16 {%0,%1,%2,%3}, [%4];"
                 : "=r"(r0), "=r"(r1), "=r"(r2), "=r"(r3) : "r"(a));
}
__device__ __forceinline__ void mma16816(float* c, const uint32_t* a, const uint32_t* b) {
    asm volatile(
        "mma.sync.aligned.m16n8k16.row.col.f32.f16.f16.f32 "
        "{%0,%1,%2,%3}, {%4,%5,%6,%7}, {%8,%9}, {%0,%1,%2,%3};"
        : "+f"(c[0]), "+f"(c[1]), "+f"(c[2]), "+f"(c[3])
        : "r"(a[0]), "r"(a[1]), "r"(a[2]), "r"(a[3]), "r"(b[0]), "r"(b[1]));
}

enum { EPI_BIAS = 0, EPI_LN = 1, EPI_UPD = 2, EPI_GELU = 3, EPI_ADD = 4 };

// ---------------------------------------------------------------------------
// fp32 -> fp16 conversion (pairs)
// ---------------------------------------------------------------------------
__global__ void f2h2(const float2* __restrict__ s, __half2* __restrict__ d, size_t n2) {
    size_t i = (size_t)blockIdx.x * blockDim.x + threadIdx.x;
    size_t st = (size_t)gridDim.x * blockDim.x;
    for (; i < n2; i += st) d[i] = __float22half2_rn(s[i]);
}

// ---------------------------------------------------------------------------
// FP16 tensor-core GEMM: y[t,n] = epi( sum_k A[t,k] W[n,k] + bias[n] )
// CTA tile 64 x 512 (full feature row -> fused LN); 8 warps, warp tile 64x64.
// ---------------------------------------------------------------------------
template<int EPI>
__global__ void __launch_bounds__(256, 1) gemm_h(
    const __half* __restrict__ A, int ldA,
    const __half* __restrict__ Wm, int K,
    const float* __restrict__ bias,
    const float* __restrict__ lng, const float* __restrict__ lnb,
    const __half* __restrict__ comp, const __half* __restrict__ target,
    const __half* __restrict__ actsP, const float* __restrict__ logit,
    const float* __restrict__ qwen,
    void* outv, int ldOut)
{
    extern __shared__ char sm[];
    const uint32_t smb = smem_u32(sm);
    const int tid = threadIdx.x, wid = tid >> 5, lane = tid & 31;
    const int g = lane >> 2, t = lane & 3;
    const size_t bm0 = (size_t)blockIdx.x * BM;
    const int colOff = blockIdx.y * 512;
    const __half* Wp = Wm + (size_t)colOff * (size_t)K;
    const int KT = K / BKH;

    float acc[4][8][4];
#pragma unroll
    for (int mi = 0; mi < 4; mi++)
#pragma unroll
        for (int ni = 0; ni < 8; ni++)
#pragma unroll
            for (int q = 0; q < 4; q++) acc[mi][ni][q] = 0.f;

    auto load_stage = [&](int buf, int kt) {
        const uint32_t sA = smb + buf * STAGE_BYTES;
        const uint32_t sB = sA + STAGE_A;
        const int k0 = kt * BKH;
#pragma unroll
        for (int i = 0; i < 2; i++) {              // A: 64 rows x 128B = 512 chunks
            int idx = tid + i * 256;
            int r = idx >> 3, ch = idx & 7;
            cp16(sA + SWZ(r * 128 + ch * 16),
                 A + (bm0 + (size_t)r) * (size_t)ldA + k0 + ch * 8);
        }
#pragma unroll
        for (int i = 0; i < 16; i++) {             // B: 512 rows x 128B = 4096 chunks
            int idx = tid + i * 256;
            int r = idx >> 3, ch = idx & 7;
            cp16(sB + SWZ(r * 128 + ch * 16),
                 Wp + (size_t)r * (size_t)K + k0 + ch * 8);
        }
    };

    load_stage(0, 0);
    asm volatile("cp.async.commit_group;\n" ::: "memory");

    for (int kt = 0; kt < KT; kt++) {
        const int buf = kt & 1;
        asm volatile("cp.async.wait_group 0;\n" ::: "memory");
        __syncthreads();                            // single barrier per K-tile
        if (kt + 1 < KT) load_stage(buf ^ 1, kt + 1);
        asm volatile("cp.async.commit_group;\n" ::: "memory");

        const uint32_t sA = smb + buf * STAGE_BYTES;
        const uint32_t sB = sA + STAGE_A;
#pragma unroll
        for (int ks = 0; ks < 4; ks++) {
            uint32_t a[4][4], b[4][4];
#pragma unroll
            for (int mi = 0; mi < 4; mi++) {
                int m  = mi * 16 + (lane & 7) + ((lane >> 3) & 1) * 8;
                int kb = ks * 32 + (lane >> 4) * 16;
                ldsm4(a[mi][0], a[mi][1], a[mi][2], a[mi][3], sA + SWZ(m * 128 + kb));
            }
#pragma unroll
            for (int p = 0; p < 4; p++) {
                int n  = wid * 64 + p * 16 + (lane >> 4) * 8 + (lane & 7);
                int kb = ks * 32 + ((lane >> 3) & 1) * 16;
                ldsm4(b[p][0], b[p][1], b[p][2], b[p][3], sB + SWZ(n * 128 + kb));
            }
#pragma unroll
            for (int mi = 0; mi < 4; mi++)
#pragma unroll
                for (int p = 0; p < 4; p++) {
                    mma16816(acc[mi][2 * p],     a[mi], &b[p][0]);
                    mma16816(acc[mi][2 * p + 1], a[mi], &b[p][2]);
                }
        }
    }
    asm volatile("cp.async.wait_group 0;\n" ::: "memory");
    __syncthreads();

    // ---------------- epilogue (smem reused: stages are dead) -----------------
    float* part = (float*)sm;            // [64 rows][8 warps][2]
    float* mrs  = (float*)sm + 1024;     // [64 rows][2]
    const float* biasP = bias + colOff;
    float*  outF = (float*)outv;
    __half* outH = (__half*)outv;

    if (EPI == EPI_LN || EPI == EPI_UPD) {
        float rs[8], rq[8];
#pragma unroll
        for (int i = 0; i < 8; i++) { rs[i] = 0.f; rq[i] = 0.f; }
#pragma unroll
        for (int ni = 0; ni < 8; ni++) {
            const int c = wid * 64 + ni * 8 + 2 * t;
            const float2 bp = *(const float2*)(biasP + c);
            float2 pp;
            if (EPI == EPI_UPD) {
                pp.x = 1.f / (1.f + expf(-logit[c]));
                pp.y = 1.f / (1.f + expf(-logit[c + 1]));
            }
#pragma unroll
            for (int mi = 0; mi < 4; mi++)
#pragma unroll
                for (int h = 0; h < 2; h++) {
                    const int r8 = mi * 2 + h;
                    const int row = mi * 16 + g + h * 8;
                    float vx = acc[mi][ni][2 * h]     + bp.x;
                    float vy = acc[mi][ni][2 * h + 1] + bp.y;
                    if (EPI == EPI_UPD) {
                        const size_t off = (bm0 + row) * DC + c;
                        float2 cv = __half22float2(*(const __half2*)(comp + off));
                        float2 tv = __half22float2(*(const __half2*)(target + off));
                        float2 av = __half22float2(*(const __half2*)(actsP + off));
                        vx = av.x + 0.5f * (cv.x - tv.x) * pp.x + 0.1f * vx;
                        vy = av.y + 0.5f * (cv.y - tv.y) * pp.y + 0.1f * vy;
                    }
                    acc[mi][ni][2 * h] = vx; acc[mi][ni][2 * h + 1] = vy;
                    rs[r8] += vx + vy;
                    rq[r8] += vx * vx + vy * vy;
                }
        }
#pragma unroll
        for (int r8 = 0; r8 < 8; r8++) {
            float s = rs[r8], q = rq[r8];
            s += __shfl_xor_sync(0xffffffffu, s, 1); q += __shfl_xor_sync(0xffffffffu, q, 1);
            s += __shfl_xor_sync(0xffffffffu, s, 2); q += __shfl_xor_sync(0xffffffffu, q, 2);
            if (t == 0) {
                const int row = (r8 >> 1) * 16 + g + (r8 & 1) * 8;
                part[row * 16 + wid * 2]     = s;
                part[row * 16 + wid * 2 + 1] = q;
            }
        }
        __syncthreads();
        if (tid < 64) {
            float s = 0.f, q = 0.f;
#pragma unroll
            for (int w = 0; w < 8; w++) { s += part[tid * 16 + w * 2]; q += part[tid * 16 + w * 2 + 1]; }
            const float mean = s * (1.f / 512.f);
            const float var  = q * (1.f / 512.f) - mean * mean;
            mrs[tid * 2]     = mean;
            mrs[tid * 2 + 1] = rsqrtf(var + 1e-5f);
        }
        __syncthreads();
#pragma unroll
        for (int ni = 0; ni < 8; ni++) {
            const int c = wid * 64 + ni * 8 + 2 * t;
            const float2 lg = *(const float2*)(lng + c);
            const float2 lb = *(const float2*)(lnb + c);
#pragma unroll
            for (int mi = 0; mi < 4; mi++)
#pragma unroll
                for (int h = 0; h < 2; h++) {
                    const int row = mi * 16 + g + h * 8;
                    const float mean = mrs[row * 2], rstd = mrs[row * 2 + 1];
                    const float yx = (acc[mi][ni][2 * h]     - mean) * rstd * lg.x + lb.x;
                    const float yy = (acc[mi][ni][2 * h + 1] - mean) * rstd * lg.y + lb.y;
                    *(__half2*)(outH + (bm0 + row) * (size_t)ldOut + c) =
                        __floats2half2_rn(yx, yy);
                }
        }
    } else {
#pragma unroll
        for (int ni = 0; ni < 8; ni++) {
            const int c = wid * 64 + ni * 8 + 2 * t;
            const float2 bp = *(const float2*)(biasP + c);
#pragma unroll
            for (int mi = 0; mi < 4; mi++)
#pragma unroll
                for (int h = 0; h < 2; h++) {
                    const int row = mi * 16 + g + h * 8;
                    float vx = acc[mi][ni][2 * h]     + bp.x;
                    float vy = acc[mi][ni][2 * h + 1] + bp.y;
                    if (EPI == EPI_GELU) {
                        vx = 0.5f * vx * (1.f + erff(vx * 0.70710678118f));
                        vy = 0.5f * vy * (1.f + erff(vy * 0.70710678118f));
                    }
                    if (EPI == EPI_ADD) {
                        const float2 qv = *(const float2*)
                            (qwen + (bm0 + row) * (size_t)DM + colOff + c);
                        float2 o; o.x = vx + qv.x; o.y = vy + qv.y;
                        *(float2*)(outF + (bm0 + row) * (size_t)ldOut + colOff + c) = o;
                    } else {
                        *(__half2*)(outH + (bm0 + row) * (size_t)ldOut + colOff + c) =
                            __floats2half2_rn(vx, vy);
                    }
                }
        }
    }
}

// ---------------------------------------------------------------------------
// Host orchestration
// ---------------------------------------------------------------------------
extern "C" void kernel_launch(void* const* d_in, const int* in_sizes, int n_in,
                              void* d_out, int out_size)
{
    const float* qwen   = (const float*)d_in[0];
    const float* obs    = (const float*)d_in[1];
    const float* proj_W = (const float*)d_in[2];
    const float* proj_b = (const float*)d_in[3];
    const float* fuse_W = (const float*)d_in[4];
    const float* fuse_b = (const float*)d_in[5];
    const float* up_W   = (const float*)d_in[6];
    const float* up_b   = (const float*)d_in[7];
    const float* lat_W  = (const float*)d_in[8];
    const float* lat_b  = (const float*)d_in[9];
    const float* plog   = (const float*)d_in[10];
    const float* ln_g   = (const float*)d_in[11];
    const float* ln_b   = (const float*)d_in[12];
    const float* down_W = (const float*)d_in[13];
    const float* down_b = (const float*)d_in[14];
    const float* out1_W = (const float*)d_in[15];
    const float* out1_b = (const float*)d_in[16];
    const float* out2_W = (const float*)d_in[17];
    const float* out2_b = (const float*)d_in[18];
    float* out = (float*)d_out;

    __half *obsh, *wh, *cat, *x0, *acts, *pred, *comp, *hbuf;
    cudaGetSymbolAddress((void**)&obsh, g_obsh);
    cudaGetSymbolAddress((void**)&wh,   g_wh);
    cudaGetSymbolAddress((void**)&cat,  g_cat);
    cudaGetSymbolAddress((void**)&x0,   g_x0);
    cudaGetSymbolAddress((void**)&acts, g_acts);
    cudaGetSymbolAddress((void**)&pred, g_pred);
    cudaGetSymbolAddress((void**)&comp, g_comp);
    cudaGetSymbolAddress((void**)&hbuf, g_h);

    cudaFuncSetAttribute(gemm_h<EPI_BIAS>, cudaFuncAttributeMaxDynamicSharedMemorySize, SMEM_BYTES);
    cudaFuncSetAttribute(gemm_h<EPI_LN>,   cudaFuncAttributeMaxDynamicSharedMemorySize, SMEM_BYTES);
    cudaFuncSetAttribute(gemm_h<EPI_UPD>,  cudaFuncAttributeMaxDynamicSharedMemorySize, SMEM_BYTES);
    cudaFuncSetAttribute(gemm_h<EPI_GELU>, cudaFuncAttributeMaxDynamicSharedMemorySize, SMEM_BYTES);
    cudaFuncSetAttribute(gemm_h<EPI_ADD>,  cudaFuncAttributeMaxDynamicSharedMemorySize, SMEM_BYTES);

    // ---- precision converts -------------------------------------------------
    auto cvt = [](const float* s, __half* d, size_t n) {
        f2h2<<<2048, 256>>>((const float2*)s, (__half2*)d, n / 2);
    };
    cvt(obs,    obsh,        (size_t)4 * TOK * DM);
    cvt(proj_W, wh + W_PROJ, (size_t)4 * DC * DM);
    cvt(fuse_W, wh + W_FUSE, (size_t)DC * 4 * DC);
    cvt(up_W,   wh + W_UP,   (size_t)4 * DC * DC);
    cvt(lat_W,  wh + W_LAT,  (size_t)4 * DC * DC);
    cvt(down_W, wh + W_DOWN, (size_t)3 * DC * DC);
    cvt(out1_W, wh + W_OUT1, (size_t)DC * DC);
    cvt(out2_W, wh + W_OUT2, (size_t)DM * DC);

    const dim3 blk(256);
    const dim3 g1(TOK / BM, 1);
    const dim3 g4(TOK / BM, 4);
    const size_t WSZ = (size_t)DC * DC;
    const size_t ASZ = (size_t)TOK * DC;

    // ---- input projections -> cat columns -----------------------------------
    for (int o = 0; o < 4; o++)
        gemm_h<EPI_BIAS><<<g1, blk, SMEM_BYTES>>>(
            obsh + (size_t)o * TOK * DM, DM,
            wh + W_PROJ + (size_t)o * DC * DM, DM, proj_b + o * DC,
            nullptr, nullptr, nullptr, nullptr, nullptr, nullptr, nullptr,
            cat + o * DC, DM);

    // ---- fuse -> x0 ----------------------------------------------------------
    gemm_h<EPI_BIAS><<<g1, blk, SMEM_BYTES>>>(
        cat, DM, wh + W_FUSE, DM, fuse_b,
        nullptr, nullptr, nullptr, nullptr, nullptr, nullptr, nullptr,
        x0, DC);

    // ---- initial bottom-up ---------------------------------------------------
    const __half* x = x0;
    for (int i = 0; i < 4; i++) {
        gemm_h<EPI_LN><<<g1, blk, SMEM_BYTES>>>(
            x, DC, wh + W_UP + i * WSZ, DC, up_b + i * DC,
            ln_g + i * DC, ln_b + i * DC,
            nullptr, nullptr, nullptr, nullptr, nullptr,
            acts + i * ASZ, DC);
        x = acts + i * ASZ;
    }

    // ---- settling ------------------------------------------------------------
    for (int s = 0; s < 5; s++) {
        gemm_h<EPI_BIAS><<<g1, blk, SMEM_BYTES>>>(
            acts + 2 * ASZ, DC, wh + W_DOWN + 2 * WSZ, DC, down_b + 2 * DC,
            nullptr, nullptr, nullptr, nullptr, nullptr, nullptr, nullptr,
            pred + 1 * ASZ, DC);
        gemm_h<EPI_BIAS><<<g1, blk, SMEM_BYTES>>>(
            acts + 1 * ASZ, DC, wh + W_DOWN + 1 * WSZ, DC, down_b + 1 * DC,
            nullptr, nullptr, nullptr, nullptr, nullptr, nullptr, nullptr,
            pred + 0 * ASZ, DC);

        x = x0;
        for (int i = 0; i < 4; i++) {
            __half* ai = acts + i * ASZ;
            gemm_h<EPI_LN><<<g1, blk, SMEM_BYTES>>>(
                x, DC, wh + W_UP + i * WSZ, DC, up_b + i * DC,
                ln_g + i * DC, ln_b + i * DC,
                nullptr, nullptr, nullptr, nullptr, nullptr,
                comp, DC);
            const __half* targ = (i < 2) ? (pred + (size_t)i * ASZ) : ai;
            gemm_h<EPI_UPD><<<g1, blk, SMEM_BYTES>>>(
                ai, DC, wh + W_LAT + i * WSZ, DC, lat_b + i * DC,
                ln_g + i * DC, ln_b + i * DC,
                comp, targ, ai, plog + i * DC, nullptr,
                ai, DC);
            x = ai;
        }
    }

    // ---- output head ---------------------------------------------------------
    gemm_h<EPI_GELU><<<g1, blk, SMEM_BYTES>>>(
        acts + 3 * ASZ, DC, wh + W_OUT1, DC, out1_b,
        nullptr, nullptr, nullptr, nullptr, nullptr, nullptr, nullptr,
        hbuf, DC);
    gemm_h<EPI_ADD><<<g4, blk, SMEM_BYTES>>>(
        hbuf, DC, wh + W_OUT2, DC, out2_b,
        nullptr, nullptr, nullptr, nullptr, nullptr, nullptr,
        qwen, out, DM);
    (void)in_sizes; (void)n_in; (void)out_size;
}

// round 4
// speedup vs baseline: 2.7276x; 1.1359x over previous
#include <cuda_runtime.h>
#include <cuda_fp16.h>
#include <cstdint>
#include <cstddef>

// ---------------------------------------------------------------------------
// Problem constants
// ---------------------------------------------------------------------------
#define TOK   8192
#define DC    512
#define DM    2048

// ---- k512 smem layout (A persistent + B double buffer + LN scratch) -------
#define KA_BYTES   65536                 // 64 rows x 512 halfs (8 col-blocks x 8192B)
#define KB_OFF     65536                 // B stage 0
#define KB_BYTES   65536                 // 512 rows x 128B
#define KSCR_OFF   196608
#define SMEM_K512  204800

// ---- gemm_big smem layout ---------------------------------------------------
#define BA_BYTES   8192                  // 64 rows x 128B per stage
#define BB_OFF     16384
#define BB_BYTES   65536
#define SMEM_BIG   147456

#define SWZ(x) ((x) ^ (((x) >> 3) & 0x70))

// ---------------------------------------------------------------------------
// Device scratch
// ---------------------------------------------------------------------------
#define W_PROJ 0
#define W_FUSE 4194304
#define W_UP   5242880
#define W_LAT  6291456
#define W_DOWN 7340032
#define W_OUT1 8126464
#define W_OUT2 8388608
__device__ __half g_wh[9437184];
__device__ __half g_cat [(size_t)TOK * DM];
__device__ __half g_x0  [TOK * DC];
__device__ __half g_acts[4 * TOK * DC];
__device__ __half g_h   [TOK * DC];

// ---------------------------------------------------------------------------
// PTX helpers
// ---------------------------------------------------------------------------
__device__ __forceinline__ uint32_t smem_u32(const void* p) {
    uint32_t a;
    asm("{ .reg .u64 t; cvta.to.shared.u64 t, %1; cvt.u32.u64 %0, t; }"
        : "=r"(a) : "l"(p));
    return a;
}
__device__ __forceinline__ void cp16(uint32_t d, const void* s) {
    asm volatile("cp.async.cg.shared.global [%0], [%1], 16;\n" :: "r"(d), "l"(s));
}
__device__ __forceinline__ void ldsm4(uint32_t& r0, uint32_t& r1,
                                      uint32_t& r2, uint32_t& r3, uint32_t a) {
    asm volatile("ldmatrix.sync.aligned.m8n8.x4.shared.b16 {%0,%1,%2,%3}, [%4];"
                 : "=r"(r0), "=r"(r1), "=r"(r2), "=r"(r3) : "r"(a));
}
__device__ __forceinline__ void mma16816(float* c, const uint32_t* a, const uint32_t* b) {
    asm volatile(
        "mma.sync.aligned.m16n8k16.row.col.f32.f16.f16.f32 "
        "{%0,%1,%2,%3}, {%4,%5,%6,%7}, {%8,%9}, {%0,%1,%2,%3};"
        : "+f"(c[0]), "+f"(c[1]), "+f"(c[2]), "+f"(c[3])
        : "r"(a[0]), "r"(a[1]), "r"(a[2]), "r"(a[3]), "r"(b[0]), "r"(b[1]));
}
#define CP_COMMIT() asm volatile("cp.async.commit_group;\n" ::: "memory")
#define CP_WAIT0()  asm volatile("cp.async.wait_group 0;\n" ::: "memory")

enum { M_LN = 0, M_UPD_P = 1, M_UPD_NP = 2, M_GELU = 3, M_ADD = 4 };

// ---------------------------------------------------------------------------
// Merged weight fp32 -> fp16 convert (all 7 arrays, one launch)
// ---------------------------------------------------------------------------
__global__ void wconv(const float2* p, const float2* f, const float2* u,
                      const float2* l, const float2* dw, const float2* o1,
                      const float2* o2, __half2* dst)
{
    const size_t N0 = 2097152, N1 = 524288, N2 = 524288, N3 = 524288,
                 N4 = 393216,  N5 = 131072, N6 = 524288;
    const size_t T = N0 + N1 + N2 + N3 + N4 + N5 + N6;
    size_t i = (size_t)blockIdx.x * blockDim.x + threadIdx.x;
    size_t st = (size_t)gridDim.x * blockDim.x;
    for (; i < T; i += st) {
        size_t j = i; const float2* s;
        if (j < N0) s = p + j;
        else { j -= N0; if (j < N1) s = f + j;
        else { j -= N1; if (j < N2) s = u + j;
        else { j -= N2; if (j < N3) s = l + j;
        else { j -= N3; if (j < N4) s = dw + j;
        else { j -= N4; if (j < N5) s = o1 + j;
        else { j -= N5; s = o2 + j; }}}}}}
        dst[i] = __float22half2_rn(*s);
    }
}

// ---------------------------------------------------------------------------
// k512: K=512 GEMM(s) with persistent-A smem + fused epilogues.
//   M_LN:     out = LN(A2 @ W2.T + b2)
//   M_UPD_P:  pred = A1@W1.T+b1 ; comp = LN(A2@W2.T+b2) ; d = comp - pred
//             out = LN(a + 0.5*sig(plog)*d + 0.1*(A3@W3.T+b3)),  a = A3 tile (smem)
//   M_UPD_NP: same, d = comp - a
//   M_GELU:   out = gelu(A2@W2.T+b2)
//   M_ADD:    out = A2@W2.T+b2 + qwen  (f32, grid.y column blocks)
// ---------------------------------------------------------------------------
template<int MODE>
__global__ void __launch_bounds__(256, 1) k512(
    const __half* __restrict__ A1, const __half* __restrict__ A2,
    const __half* __restrict__ A3,
    const __half* __restrict__ W1, const __half* __restrict__ W2,
    const __half* __restrict__ W3,
    const float* __restrict__ b1, const float* __restrict__ b2,
    const float* __restrict__ b3,
    const float* __restrict__ lng, const float* __restrict__ lnb,
    const float* __restrict__ plog,
    const float* __restrict__ qwen, void* outv, int ldOut)
{
    extern __shared__ char sm[];
    const uint32_t smb = smem_u32(sm);
    const int tid = threadIdx.x, wid = tid >> 5, lane = tid & 31;
    const int g = lane >> 2, t = lane & 3;
    const size_t bm0 = (size_t)blockIdx.x * 64;
    const int colOff = blockIdx.y * 512;
    if (MODE == M_ADD) { W2 += (size_t)colOff * DC; b2 += colOff; }

    float acc[4][8][4];
    uint32_t stash[4][8][2];             // half2 pred/diff/comp (UPD modes only)
    float* part = (float*)(sm + KSCR_OFF);
    float* mrs  = (float*)(sm + KSCR_OFF + 4096);

    auto loadA = [&](const __half* Ap) {
        __syncthreads();
#pragma unroll
        for (int i = 0; i < 16; i++) {
            int idx = tid + i * 256; int r = idx >> 6, c = idx & 63;
            cp16(smb + ((c >> 3) << 13) + SWZ(r * 128 + (c & 7) * 16),
                 Ap + (bm0 + (size_t)r) * DC + c * 8);
        }
    };

    auto run_gemm = [&](const __half* W) {
#pragma unroll
        for (int mi = 0; mi < 4; mi++)
#pragma unroll
            for (int ni = 0; ni < 8; ni++)
#pragma unroll
                for (int q = 0; q < 4; q++) acc[mi][ni][q] = 0.f;
        auto loadB = [&](int buf, int kt) {
            const uint32_t sB = smb + KB_OFF + buf * KB_BYTES;
            const int k0 = kt * 64;
#pragma unroll
            for (int i = 0; i < 16; i++) {
                int idx = tid + i * 256; int r = idx >> 3, ch = idx & 7;
                cp16(sB + SWZ(r * 128 + ch * 16),
                     W + (size_t)r * DC + k0 + ch * 8);
            }
        };
        loadB(0, 0);
        CP_COMMIT();
        for (int kt = 0; kt < 8; kt++) {
            CP_WAIT0();
            __syncthreads();
            if (kt < 7) loadB((kt + 1) & 1, kt + 1);
            CP_COMMIT();
            const uint32_t sA = smb + kt * 8192;
            const uint32_t sB = smb + KB_OFF + (kt & 1) * KB_BYTES;
#pragma unroll
            for (int ks = 0; ks < 4; ks++) {
                uint32_t a[4][4], b[4][4];
#pragma unroll
                for (int mi = 0; mi < 4; mi++) {
                    int m  = mi * 16 + (lane & 7) + ((lane >> 3) & 1) * 8;
                    int kb = ks * 32 + (lane >> 4) * 16;
                    ldsm4(a[mi][0], a[mi][1], a[mi][2], a[mi][3], sA + SWZ(m * 128 + kb));
                }
#pragma unroll
                for (int p = 0; p < 4; p++) {
                    int n  = wid * 64 + p * 16 + (lane >> 4) * 8 + (lane & 7);
                    int kb = ks * 32 + ((lane >> 3) & 1) * 16;
                    ldsm4(b[p][0], b[p][1], b[p][2], b[p][3], sB + SWZ(n * 128 + kb));
                }
#pragma unroll
                for (int mi = 0; mi < 4; mi++)
#pragma unroll
                    for (int p = 0; p < 4; p++) {
                        mma16816(acc[mi][2 * p],     a[mi], &b[p][0]);
                        mma16816(acc[mi][2 * p + 1], a[mi], &b[p][2]);
                    }
            }
        }
    };

    // LN stats over acc (values must already include bias/extra terms)
    auto ln_stats = [&]() {
        float rs[8], rq[8];
#pragma unroll
        for (int i = 0; i < 8; i++) { rs[i] = 0.f; rq[i] = 0.f; }
#pragma unroll
        for (int ni = 0; ni < 8; ni++)
#pragma unroll
            for (int mi = 0; mi < 4; mi++)
#pragma unroll
                for (int h = 0; h < 2; h++) {
                    float vx = acc[mi][ni][2 * h], vy = acc[mi][ni][2 * h + 1];
                    rs[mi * 2 + h] += vx + vy;
                    rq[mi * 2 + h] += vx * vx + vy * vy;
                }
#pragma unroll
        for (int r8 = 0; r8 < 8; r8++) {
            float s = rs[r8], q = rq[r8];
            s += __shfl_xor_sync(0xffffffffu, s, 1); q += __shfl_xor_sync(0xffffffffu, q, 1);
            s += __shfl_xor_sync(0xffffffffu, s, 2); q += __shfl_xor_sync(0xffffffffu, q, 2);
            if (t == 0) {
                const int row = (r8 >> 1) * 16 + g + (r8 & 1) * 8;
                part[row * 16 + wid * 2]     = s;
                part[row * 16 + wid * 2 + 1] = q;
            }
        }
        __syncthreads();
        if (tid < 64) {
            float s = 0.f, q = 0.f;
#pragma unroll
            for (int w = 0; w < 8; w++) { s += part[tid * 16 + w * 2]; q += part[tid * 16 + w * 2 + 1]; }
            const float mean = s * (1.f / 512.f);
            const float var  = q * (1.f / 512.f) - mean * mean;
            mrs[tid * 2]     = mean;
            mrs[tid * 2 + 1] = rsqrtf(var + 1e-5f);
        }
        __syncthreads();
    };

    __half* outH = (__half*)outv;
    float*  outF = (float*)outv;

    // ---------------- phase 1: pred (UPD_P only) -------------------------------
    if (MODE == M_UPD_P) {
        loadA(A1);
        run_gemm(W1);
#pragma unroll
        for (int ni = 0; ni < 8; ni++) {
            const int c = wid * 64 + ni * 8 + 2 * t;
            const float2 bp = *(const float2*)(b1 + c);
#pragma unroll
            for (int mi = 0; mi < 4; mi++)
#pragma unroll
                for (int h = 0; h < 2; h++) {
                    __half2 hv = __floats2half2_rn(acc[mi][ni][2 * h] + bp.x,
                                                   acc[mi][ni][2 * h + 1] + bp.y);
                    stash[mi][ni][h] = *(uint32_t*)&hv;
                }
        }
    }

    // ---------------- phase 2: main / comp GEMM --------------------------------
    loadA(A2);
    run_gemm(W2);

    if (MODE == M_LN || MODE == M_UPD_P || MODE == M_UPD_NP) {
#pragma unroll
        for (int ni = 0; ni < 8; ni++) {
            const int c = wid * 64 + ni * 8 + 2 * t;
            const float2 bp = *(const float2*)(b2 + c);
#pragma unroll
            for (int mi = 0; mi < 4; mi++)
#pragma unroll
                for (int h = 0; h < 2; h++) {
                    acc[mi][ni][2 * h]     += bp.x;
                    acc[mi][ni][2 * h + 1] += bp.y;
                }
        }
        ln_stats();
#pragma unroll
        for (int ni = 0; ni < 8; ni++) {
            const int c = wid * 64 + ni * 8 + 2 * t;
            const float2 lg = *(const float2*)(lng + c);
            const float2 lb = *(const float2*)(lnb + c);
#pragma unroll
            for (int mi = 0; mi < 4; mi++)
#pragma unroll
                for (int h = 0; h < 2; h++) {
                    const int row = mi * 16 + g + h * 8;
                    const float mean = mrs[row * 2], rstd = mrs[row * 2 + 1];
                    const float cx = (acc[mi][ni][2 * h]     - mean) * rstd * lg.x + lb.x;
                    const float cy = (acc[mi][ni][2 * h + 1] - mean) * rstd * lg.y + lb.y;
                    if (MODE == M_LN) {
                        *(__half2*)(outH + (bm0 + row) * (size_t)ldOut + c) =
                            __floats2half2_rn(cx, cy);
                    } else if (MODE == M_UPD_P) {
                        __half2 pv = *(__half2*)&stash[mi][ni][h];
                        float2 pf = __half22float2(pv);
                        __half2 dv = __floats2half2_rn(cx - pf.x, cy - pf.y);
                        stash[mi][ni][h] = *(uint32_t*)&dv;
                    } else {  // M_UPD_NP: stash comp
                        __half2 cv = __floats2half2_rn(cx, cy);
                        stash[mi][ni][h] = *(uint32_t*)&cv;
                    }
                }
        }
    } else {
        // GELU / ADD epilogues
#pragma unroll
        for (int ni = 0; ni < 8; ni++) {
            const int c = wid * 64 + ni * 8 + 2 * t;
            const float2 bp = *(const float2*)(b2 + c);
#pragma unroll
            for (int mi = 0; mi < 4; mi++)
#pragma unroll
                for (int h = 0; h < 2; h++) {
                    const int row = mi * 16 + g + h * 8;
                    float vx = acc[mi][ni][2 * h]     + bp.x;
                    float vy = acc[mi][ni][2 * h + 1] + bp.y;
                    if (MODE == M_GELU) {
                        vx = 0.5f * vx * (1.f + erff(vx * 0.70710678118f));
                        vy = 0.5f * vy * (1.f + erff(vy * 0.70710678118f));
                        *(__half2*)(outH + (bm0 + row) * (size_t)ldOut + c) =
                            __floats2half2_rn(vx, vy);
                    } else {  // M_ADD
                        const float2 qv = *(const float2*)
                            (qwen + (bm0 + row) * (size_t)DM + colOff + c);
                        float2 o; o.x = vx + qv.x; o.y = vy + qv.y;
                        *(float2*)(outF + (bm0 + row) * (size_t)ldOut + colOff + c) = o;
                    }
                }
        }
    }

    // ---------------- phase 3: lateral GEMM + update + LN ----------------------
    if (MODE == M_UPD_P || MODE == M_UPD_NP) {
        loadA(A3);                      // A3 = acts[i]; also the 'a' operand
        run_gemm(W3);
#pragma unroll
        for (int ni = 0; ni < 8; ni++) {
            const int c = wid * 64 + ni * 8 + 2 * t;
            const float2 bp = *(const float2*)(b3 + c);
            const float px = 1.f / (1.f + expf(-plog[c]));
            const float py = 1.f / (1.f + expf(-plog[c + 1]));
            const uint32_t cblk = ((uint32_t)(c >> 6) << 13);
            const uint32_t cin  = (uint32_t)(c & 63) * 2;
#pragma unroll
            for (int mi = 0; mi < 4; mi++)
#pragma unroll
                for (int h = 0; h < 2; h++) {
                    const int row = mi * 16 + g + h * 8;
                    __half2 ah = *(__half2*)(sm + cblk + SWZ((uint32_t)row * 128 + cin));
                    float2 af = __half22float2(ah);
                    float2 sf = __half22float2(*(__half2*)&stash[mi][ni][h]);
                    float dx, dy;
                    if (MODE == M_UPD_P) { dx = sf.x; dy = sf.y; }
                    else                 { dx = sf.x - af.x; dy = sf.y - af.y; }
                    acc[mi][ni][2 * h] =
                        af.x + 0.5f * px * dx + 0.1f * (acc[mi][ni][2 * h] + bp.x);
                    acc[mi][ni][2 * h + 1] =
                        af.y + 0.5f * py * dy + 0.1f * (acc[mi][ni][2 * h + 1] + bp.y);
                }
        }
        ln_stats();
#pragma unroll
        for (int ni = 0; ni < 8; ni++) {
            const int c = wid * 64 + ni * 8 + 2 * t;
            const float2 lg = *(const float2*)(lng + c);
            const float2 lb = *(const float2*)(lnb + c);
#pragma unroll
            for (int mi = 0; mi < 4; mi++)
#pragma unroll
                for (int h = 0; h < 2; h++) {
                    const int row = mi * 16 + g + h * 8;
                    const float mean = mrs[row * 2], rstd = mrs[row * 2 + 1];
                    const float yx = (acc[mi][ni][2 * h]     - mean) * rstd * lg.x + lb.x;
                    const float yy = (acc[mi][ni][2 * h + 1] - mean) * rstd * lg.y + lb.y;
                    *(__half2*)(outH + (bm0 + row) * (size_t)ldOut + c) =
                        __floats2half2_rn(yx, yy);
                }
        }
    }
}

// ---------------------------------------------------------------------------
// gemm_big: K=2048 GEMM, bias epilogue, half output.
//   AF32=1: A read as fp32 (obs), converted in-flight; blockIdx.z = obs index.
//   AF32=0: A is half (cat).
// ---------------------------------------------------------------------------
template<int AF32>
__global__ void __launch_bounds__(256, 1) gemm_big(
    const void* Av, const __half* __restrict__ Wall,
    const float* __restrict__ bias, __half* out, int ldOut)
{
    extern __shared__ char sm[];
    const uint32_t smb = smem_u32(sm);
    const int tid = threadIdx.x, wid = tid >> 5, lane = tid & 31;
    const int g = lane >> 2, t = lane & 3;
    const size_t bm0 = (size_t)blockIdx.x * 64;
    const int o = blockIdx.z;
    const float*  Af = (const float*)Av + (size_t)o * TOK * DM;
    const __half* Ah = (const __half*)Av;
    const __half* W  = Wall + (size_t)o * DC * DM;
    const float*  bp = bias + o * DC;
    __half* outp = out + o * 512;

    float acc[4][8][4];
#pragma unroll
    for (int mi = 0; mi < 4; mi++)
#pragma unroll
        for (int ni = 0; ni < 8; ni++)
#pragma unroll
            for (int q = 0; q < 4; q++) acc[mi][ni][q] = 0.f;

    float fr[16];
    auto ldgA = [&](int kt) {
        const int k0 = kt * 64;
#pragma unroll
        for (int i = 0; i < 2; i++) {
            int idx = tid + i * 256; int r = idx >> 3, ch = idx & 7;
            const float4* s = (const float4*)(Af + (bm0 + r) * (size_t)DM + k0 + ch * 8);
            float4 x0 = s[0], x1 = s[1];
            fr[i * 8 + 0] = x0.x; fr[i * 8 + 1] = x0.y; fr[i * 8 + 2] = x0.z; fr[i * 8 + 3] = x0.w;
            fr[i * 8 + 4] = x1.x; fr[i * 8 + 5] = x1.y; fr[i * 8 + 6] = x1.z; fr[i * 8 + 7] = x1.w;
        }
    };
    auto stsA = [&](int buf) {
        const uint32_t sA = smb + buf * BA_BYTES;
#pragma unroll
        for (int i = 0; i < 2; i++) {
            int idx = tid + i * 256; int r = idx >> 3, ch = idx & 7;
            __half2 h0 = __floats2half2_rn(fr[i * 8 + 0], fr[i * 8 + 1]);
            __half2 h1 = __floats2half2_rn(fr[i * 8 + 2], fr[i * 8 + 3]);
            __half2 h2 = __floats2half2_rn(fr[i * 8 + 4], fr[i * 8 + 5]);
            __half2 h3 = __floats2half2_rn(fr[i * 8 + 6], fr[i * 8 + 7]);
            asm volatile("st.shared.v4.b32 [%0], {%1,%2,%3,%4};"
                :: "r"(sA + SWZ(r * 128 + ch * 16)),
                   "r"(*(uint32_t*)&h0), "r"(*(uint32_t*)&h1),
                   "r"(*(uint32_t*)&h2), "r"(*(uint32_t*)&h3));
        }
    };
    auto loadAh = [&](int buf, int kt) {
        const uint32_t sA = smb + buf * BA_BYTES;
        const int k0 = kt * 64;
#pragma unroll
        for (int i = 0; i < 2; i++) {
            int idx = tid + i * 256; int r = idx >> 3, ch = idx & 7;
            cp16(sA + SWZ(r * 128 + ch * 16), Ah + (bm0 + r) * (size_t)DM + k0 + ch * 8);
        }
    };
    auto loadB = [&](int buf, int kt) {
        const uint32_t sB = smb + BB_OFF + buf * BB_BYTES;
        const int k0 = kt * 64;
#pragma unroll
        for (int i = 0; i < 16; i++) {
            int idx = tid + i * 256; int r = idx >> 3, ch = idx & 7;
            cp16(sB + SWZ(r * 128 + ch * 16), W + (size_t)r * DM + k0 + ch * 8);
        }
    };

    if (AF32) ldgA(0); else loadAh(0, 0);
    loadB(0, 0);
    CP_COMMIT();
    for (int kt = 0; kt < 32; kt++) {
        CP_WAIT0();
        __syncthreads();
        if (AF32) {
            stsA(kt & 1);
            if (kt < 31) ldgA(kt + 1);
        }
        if (kt < 31) {
            if (!AF32) loadAh((kt + 1) & 1, kt + 1);
            loadB((kt + 1) & 1, kt + 1);
        }
        CP_COMMIT();
        if (AF32) __syncthreads();
        const uint32_t sA = smb + (kt & 1) * BA_BYTES;
        const uint32_t sB = smb + BB_OFF + (kt & 1) * BB_BYTES;
#pragma unroll
        for (int ks = 0; ks < 4; ks++) {
            uint32_t a[4][4], b[4][4];
#pragma unroll
            for (int mi = 0; mi < 4; mi++) {
                int m  = mi * 16 + (lane & 7) + ((lane >> 3) & 1) * 8;
                int kb = ks * 32 + (lane >> 4) * 16;
                ldsm4(a[mi][0], a[mi][1], a[mi][2], a[mi][3], sA + SWZ(m * 128 + kb));
            }
#pragma unroll
            for (int p = 0; p < 4; p++) {
                int n  = wid * 64 + p * 16 + (lane >> 4) * 8 + (lane & 7);
                int kb = ks * 32 + ((lane >> 3) & 1) * 16;
                ldsm4(b[p][0], b[p][1], b[p][2], b[p][3], sB + SWZ(n * 128 + kb));
            }
#pragma unroll
            for (int mi = 0; mi < 4; mi++)
#pragma unroll
                for (int p = 0; p < 4; p++) {
                    mma16816(acc[mi][2 * p],     a[mi], &b[p][0]);
                    mma16816(acc[mi][2 * p + 1], a[mi], &b[p][2]);
                }
        }
    }

    // bias epilogue -> half
#pragma unroll
    for (int ni = 0; ni < 8; ni++) {
        const int c = wid * 64 + ni * 8 + 2 * t;
        const float2 b2 = *(const float2*)(bp + c);
#pragma unroll
        for (int mi = 0; mi < 4; mi++)
#pragma unroll
            for (int h = 0; h < 2; h++) {
                const int row = mi * 16 + g + h * 8;
                *(__half2*)(outp + (bm0 + row) * (size_t)ldOut + c) =
                    __floats2half2_rn(acc[mi][ni][2 * h] + b2.x,
                                      acc[mi][ni][2 * h + 1] + b2.y);
            }
    }
}

// ---------------------------------------------------------------------------
// Host orchestration (32 launches, fully capturable)
// ---------------------------------------------------------------------------
extern "C" void kernel_launch(void* const* d_in, const int* in_sizes, int n_in,
                              void* d_out, int out_size)
{
    const float* qwen   = (const float*)d_in[0];
    const float* obs    = (const float*)d_in[1];
    const float* proj_W = (const float*)d_in[2];
    const float* proj_b = (const float*)d_in[3];
    const float* fuse_W = (const float*)d_in[4];
    const float* fuse_b = (const float*)d_in[5];
    const float* up_W   = (const float*)d_in[6];
    const float* up_b   = (const float*)d_in[7];
    const float* lat_W  = (const float*)d_in[8];
    const float* lat_b  = (const float*)d_in[9];
    const float* plog   = (const float*)d_in[10];
    const float* ln_g   = (const float*)d_in[11];
    const float* ln_b   = (const float*)d_in[12];
    const float* down_W = (const float*)d_in[13];
    const float* down_b = (const float*)d_in[14];
    const float* out1_W = (const float*)d_in[15];
    const float* out1_b = (const float*)d_in[16];
    const float* out2_W = (const float*)d_in[17];
    const float* out2_b = (const float*)d_in[18];
    float* out = (float*)d_out;

    __half *wh, *cat, *x0, *acts, *hbuf;
    cudaGetSymbolAddress((void**)&wh,   g_wh);
    cudaGetSymbolAddress((void**)&cat,  g_cat);
    cudaGetSymbolAddress((void**)&x0,   g_x0);
    cudaGetSymbolAddress((void**)&acts, g_acts);
    cudaGetSymbolAddress((void**)&hbuf, g_h);

    cudaFuncSetAttribute(k512<M_LN>,     cudaFuncAttributeMaxDynamicSharedMemorySize, SMEM_K512);
    cudaFuncSetAttribute(k512<M_UPD_P>,  cudaFuncAttributeMaxDynamicSharedMemorySize, SMEM_K512);
    cudaFuncSetAttribute(k512<M_UPD_NP>, cudaFuncAttributeMaxDynamicSharedMemorySize, SMEM_K512);
    cudaFuncSetAttribute(k512<M_GELU>,   cudaFuncAttributeMaxDynamicSharedMemorySize, SMEM_K512);
    cudaFuncSetAttribute(k512<M_ADD>,    cudaFuncAttributeMaxDynamicSharedMemorySize, SMEM_K512);
    cudaFuncSetAttribute(gemm_big<0>,    cudaFuncAttributeMaxDynamicSharedMemorySize, SMEM_BIG);
    cudaFuncSetAttribute(gemm_big<1>,    cudaFuncAttributeMaxDynamicSharedMemorySize, SMEM_BIG);

    const dim3 blk(256);
    const size_t WSZ = (size_t)DC * DC;
    const size_t ASZ = (size_t)TOK * DC;

    // 1) weight converts (one launch)
    wconv<<<1024, blk>>>((const float2*)proj_W, (const float2*)fuse_W,
                         (const float2*)up_W,   (const float2*)lat_W,
                         (const float2*)down_W, (const float2*)out1_W,
                         (const float2*)out2_W, (__half2*)wh);

    // 2) 4 input projections (one launch, blockIdx.z = o; reads obs fp32 directly)
    gemm_big<1><<<dim3(TOK / 64, 1, 4), blk, SMEM_BIG>>>(
        obs, wh + W_PROJ, proj_b, cat, DM);

    // 3) fuse -> x0
    gemm_big<0><<<dim3(TOK / 64, 1, 1), blk, SMEM_BIG>>>(
        cat, wh + W_FUSE, fuse_b, x0, DC);

    // 4) initial bottom-up
    const __half* x = x0;
    for (int i = 0; i < 4; i++) {
        k512<M_LN><<<TOK / 64, blk, SMEM_K512>>>(
            nullptr, x, nullptr,
            nullptr, wh + W_UP + i * WSZ, nullptr,
            nullptr, up_b + i * DC, nullptr,
            ln_g + i * DC, ln_b + i * DC, nullptr,
            nullptr, acts + i * ASZ, DC);
        x = acts + i * ASZ;
    }

    // 5) settling: 4 fused layer kernels per iteration
    for (int s = 0; s < 5; s++) {
        // layer 0 (pred from acts[1], pre-sweep)
        k512<M_UPD_P><<<TOK / 64, blk, SMEM_K512>>>(
            acts + 1 * ASZ, x0, acts + 0 * ASZ,
            wh + W_DOWN + 1 * WSZ, wh + W_UP + 0 * WSZ, wh + W_LAT + 0 * WSZ,
            down_b + 1 * DC, up_b + 0 * DC, lat_b + 0 * DC,
            ln_g + 0 * DC, ln_b + 0 * DC, plog + 0 * DC,
            nullptr, acts + 0 * ASZ, DC);
        // layer 1 (pred from acts[2], pre-sweep)
        k512<M_UPD_P><<<TOK / 64, blk, SMEM_K512>>>(
            acts + 2 * ASZ, acts + 0 * ASZ, acts + 1 * ASZ,
            wh + W_DOWN + 2 * WSZ, wh + W_UP + 1 * WSZ, wh + W_LAT + 1 * WSZ,
            down_b + 2 * DC, up_b + 1 * DC, lat_b + 1 * DC,
            ln_g + 1 * DC, ln_b + 1 * DC, plog + 1 * DC,
            nullptr, acts + 1 * ASZ, DC);
        // layer 2 (target = old acts[2])
        k512<M_UPD_NP><<<TOK / 64, blk, SMEM_K512>>>(
            nullptr, acts + 1 * ASZ, acts + 2 * ASZ,
            nullptr, wh + W_UP + 2 * WSZ, wh + W_LAT + 2 * WSZ,
            nullptr, up_b + 2 * DC, lat_b + 2 * DC,
            ln_g + 2 * DC, ln_b + 2 * DC, plog + 2 * DC,
            nullptr, acts + 2 * ASZ, DC);
        // layer 3
        k512<M_UPD_NP><<<TOK / 64, blk, SMEM_K512>>>(
            nullptr, acts + 2 * ASZ, acts + 3 * ASZ,
            nullptr, wh + W_UP + 3 * WSZ, wh + W_LAT + 3 * WSZ,
            nullptr, up_b + 3 * DC, lat_b + 3 * DC,
            ln_g + 3 * DC, ln_b + 3 * DC, plog + 3 * DC,
            nullptr, acts + 3 * ASZ, DC);
    }

    // 6) head
    k512<M_GELU><<<TOK / 64, blk, SMEM_K512>>>(
        nullptr, acts + 3 * ASZ, nullptr,
        nullptr, wh + W_OUT1, nullptr,
        nullptr, out1_b, nullptr,
        nullptr, nullptr, nullptr,
        nullptr, hbuf, DC);
    k512<M_ADD><<<dim3(TOK / 64, 4), blk, SMEM_K512>>>(
        nullptr, hbuf, nullptr,
        nullptr, wh + W_OUT2, nullptr,
        nullptr, out2_b, nullptr,
        nullptr, nullptr, nullptr,
        qwen, out, DM);
    (void)in_sizes; (void)n_in; (void)out_size;
}